// round 6
// baseline (speedup 1.0000x reference)
#include <cuda_runtime.h>
#include <cstdint>

// Inputs (metadata order):
//   d_in[0]: data       float32 [200000, 5]
//   d_in[1]: clusts     int32   [1024, 128]
//   d_in[2]: edge_index int32   [2, N_EDGES]
// Output: float32 [2*N_EDGES, 19]

#define P 128  // points per cluster

__global__ __launch_bounds__(P, 8)
void clust_geo_edge_kernel(const float* __restrict__ data,
                           const int* __restrict__ clusts,
                           const int* __restrict__ eidx,
                           float* __restrict__ out,
                           int n_edges) {
    const int e = blockIdx.x;
    const int t = threadIdx.x;  // 0..127, thread t owns row i1 = t

    __shared__ float4 p1[P];
    __shared__ float4 p2[P];
    __shared__ unsigned long long wmin[4];

    const int c1 = eidx[e];
    const int c2 = eidx[n_edges + e];

    // Gather the two point sets (coords = data[:,1:4])
    {
        int v1 = clusts[c1 * P + t];
        const float* r1 = data + (size_t)v1 * 5;
        p1[t] = make_float4(__ldg(r1 + 1), __ldg(r1 + 2), __ldg(r1 + 3), 0.0f);

        int v2 = clusts[c2 * P + t];
        const float* r2 = data + (size_t)v2 * 5;
        p2[t] = make_float4(__ldg(r2 + 1), __ldg(r2 + 2), __ldg(r2 + 3), 0.0f);
    }
    __syncthreads();

    const float ax = p1[t].x, ay = p1[t].y, az = p1[t].z;

    // Per-thread scan over all 128 columns. Strict < keeps earliest j on ties.
    // Intrinsics forbid FMA contraction so d2 rounding matches the reference:
    //   d2 = ((dx*dx) + (dy*dy)) + (dz*dz)
    float bestV = 3.402823466e+38f;
    int   bestJ = 0;
    #pragma unroll 8
    for (int j = 0; j < P; ++j) {
        float4 b = p2[j];  // warp-broadcast LDS.128
        float dx = __fsub_rn(ax, b.x);
        float dy = __fsub_rn(ay, b.y);
        float dz = __fsub_rn(az, b.z);
        float d2 = __fadd_rn(__fadd_rn(__fmul_rn(dx, dx), __fmul_rn(dy, dy)),
                             __fmul_rn(dz, dz));
        if (d2 < bestV) { bestV = d2; bestJ = j; }
    }

    // Pack (value bits, flat index) into u64; d2 >= 0 so float bits are
    // order-preserving. min() over keys = argmin with first-occurrence tie-break.
    unsigned long long key =
        ((unsigned long long)__float_as_uint(bestV) << 32) |
        (unsigned int)(t * P + bestJ);

    #pragma unroll
    for (int o = 16; o > 0; o >>= 1) {
        unsigned long long other = __shfl_down_sync(0xffffffffu, key, o);
        key = (other < key) ? other : key;
    }
    if ((t & 31) == 0) wmin[t >> 5] = key;
    __syncthreads();

    if (t == 0) {
        unsigned long long k = wmin[0];
        k = (wmin[1] < k) ? wmin[1] : k;
        k = (wmin[2] < k) ? wmin[2] : k;
        k = (wmin[3] < k) ? wmin[3] : k;
        const int flat = (int)(k & 0xFFFFFFFFu);
        const int i1 = flat >> 7;
        const int i2 = flat & (P - 1);

        const float4 a = p1[i1];
        const float4 b = p2[i2];

        const float dx = __fsub_rn(a.x, b.x);
        const float dy = __fsub_rn(a.y, b.y);
        const float dz = __fsub_rn(a.z, b.z);
        const float ss = __fadd_rn(__fadd_rn(__fmul_rn(dx, dx), __fmul_rn(dy, dy)),
                                   __fmul_rn(dz, dz));
        const float lend = sqrtf(ss);

        float nx, ny, nz;
        if (lend > 0.0f) {
            nx = __fdiv_rn(dx, lend);
            ny = __fdiv_rn(dy, lend);
            nz = __fdiv_rn(dz, lend);
        } else {
            nx = dx; ny = dy; nz = dz;
        }

        float B[9];
        B[0] = __fmul_rn(nx, nx); B[1] = __fmul_rn(nx, ny); B[2] = __fmul_rn(nx, nz);
        B[3] = __fmul_rn(ny, nx); B[4] = __fmul_rn(ny, ny); B[5] = __fmul_rn(ny, nz);
        B[6] = __fmul_rn(nz, nx); B[7] = __fmul_rn(nz, ny); B[8] = __fmul_rn(nz, nz);

        float* o0 = out + (size_t)(2 * e) * 19;      // feats
        float* o1 = o0 + 19;                          // feats_flip

        o0[0] = a.x;  o0[1] = a.y;  o0[2] = a.z;
        o0[3] = b.x;  o0[4] = b.y;  o0[5] = b.z;
        o0[6] = nx;   o0[7] = ny;   o0[8] = nz;
        o0[9] = lend;
        #pragma unroll
        for (int i = 0; i < 9; ++i) o0[10 + i] = B[i];

        o1[0] = b.x;  o1[1] = b.y;  o1[2] = b.z;
        o1[3] = a.x;  o1[4] = a.y;  o1[5] = a.z;
        o1[6] = -nx;  o1[7] = -ny;  o1[8] = -nz;
        o1[9] = lend;
        #pragma unroll
        for (int i = 0; i < 9; ++i) o1[10 + i] = B[i];
    }
}

extern "C" void kernel_launch(void* const* d_in, const int* in_sizes, int n_in,
                              void* d_out, int out_size) {
    const float* data   = (const float*)d_in[0];
    const int*   clusts = (const int*)d_in[1];
    const int*   eidx   = (const int*)d_in[2];
    float*       out    = (float*)d_out;

    const int n_edges = in_sizes[2] / 2;

    clust_geo_edge_kernel<<<n_edges, P>>>(data, clusts, eidx, out, n_edges);
}

// round 7
// speedup vs baseline: 1.0043x; 1.0043x over previous
#include <cuda_runtime.h>
#include <cstdint>

// Inputs (metadata order):
//   d_in[0]: data       float32 [200000, 5]
//   d_in[1]: clusts     int32   [1024, 128]
//   d_in[2]: edge_index int32   [2, N_EDGES]
// Output: float32 [2*N_EDGES, 19]

#define P 128  // points per cluster

__global__ __launch_bounds__(P, 8)
void clust_geo_edge_kernel(const float* __restrict__ data,
                           const int* __restrict__ clusts,
                           const int* __restrict__ eidx,
                           float* __restrict__ out,
                           int n_edges) {
    const int e = blockIdx.x;
    const int t = threadIdx.x;  // 0..127, thread t owns row i1 = t

    __shared__ float4 p1[P];
    __shared__ float4 p2[P];
    __shared__ unsigned long long wmin[4];

    const int c1 = eidx[e];
    const int c2 = eidx[n_edges + e];

    // Gather the two point sets (coords = data[:,1:4])
    {
        int v1 = clusts[c1 * P + t];
        const float* r1 = data + (size_t)v1 * 5;
        p1[t] = make_float4(__ldg(r1 + 1), __ldg(r1 + 2), __ldg(r1 + 3), 0.0f);

        int v2 = clusts[c2 * P + t];
        const float* r2 = data + (size_t)v2 * 5;
        p2[t] = make_float4(__ldg(r2 + 1), __ldg(r2 + 2), __ldg(r2 + 3), 0.0f);
    }
    __syncthreads();

    const float ax = p1[t].x, ay = p1[t].y, az = p1[t].z;

    // Per-thread scan over all 128 columns. Strict < keeps earliest j on ties.
    // Intrinsics forbid FMA contraction so d2 rounding matches the reference:
    //   d2 = ((dx*dx) + (dy*dy)) + (dz*dz)
    float bestV = 3.402823466e+38f;
    int   bestJ = 0;
    #pragma unroll 8
    for (int j = 0; j < P; ++j) {
        float4 b = p2[j];  // warp-broadcast LDS.128
        float dx = __fsub_rn(ax, b.x);
        float dy = __fsub_rn(ay, b.y);
        float dz = __fsub_rn(az, b.z);
        float d2 = __fadd_rn(__fadd_rn(__fmul_rn(dx, dx), __fmul_rn(dy, dy)),
                             __fmul_rn(dz, dz));
        if (d2 < bestV) { bestV = d2; bestJ = j; }
    }

    // Pack (value bits, flat index) into u64; d2 >= 0 so float bits are
    // order-preserving. min() over keys = argmin with first-occurrence tie-break.
    unsigned long long key =
        ((unsigned long long)__float_as_uint(bestV) << 32) |
        (unsigned int)(t * P + bestJ);

    #pragma unroll
    for (int o = 16; o > 0; o >>= 1) {
        unsigned long long other = __shfl_down_sync(0xffffffffu, key, o);
        key = (other < key) ? other : key;
    }
    if ((t & 31) == 0) wmin[t >> 5] = key;
    __syncthreads();

    if (t == 0) {
        unsigned long long k = wmin[0];
        k = (wmin[1] < k) ? wmin[1] : k;
        k = (wmin[2] < k) ? wmin[2] : k;
        k = (wmin[3] < k) ? wmin[3] : k;
        const int flat = (int)(k & 0xFFFFFFFFu);
        const int i1 = flat >> 7;
        const int i2 = flat & (P - 1);

        const float4 a = p1[i1];
        const float4 b = p2[i2];

        const float dx = __fsub_rn(a.x, b.x);
        const float dy = __fsub_rn(a.y, b.y);
        const float dz = __fsub_rn(a.z, b.z);
        const float ss = __fadd_rn(__fadd_rn(__fmul_rn(dx, dx), __fmul_rn(dy, dy)),
                                   __fmul_rn(dz, dz));
        const float lend = sqrtf(ss);

        float nx, ny, nz;
        if (lend > 0.0f) {
            nx = __fdiv_rn(dx, lend);
            ny = __fdiv_rn(dy, lend);
            nz = __fdiv_rn(dz, lend);
        } else {
            nx = dx; ny = dy; nz = dz;
        }

        float B[9];
        B[0] = __fmul_rn(nx, nx); B[1] = __fmul_rn(nx, ny); B[2] = __fmul_rn(nx, nz);
        B[3] = __fmul_rn(ny, nx); B[4] = __fmul_rn(ny, ny); B[5] = __fmul_rn(ny, nz);
        B[6] = __fmul_rn(nz, nx); B[7] = __fmul_rn(nz, ny); B[8] = __fmul_rn(nz, nz);

        float* o0 = out + (size_t)(2 * e) * 19;      // feats
        float* o1 = o0 + 19;                          // feats_flip

        o0[0] = a.x;  o0[1] = a.y;  o0[2] = a.z;
        o0[3] = b.x;  o0[4] = b.y;  o0[5] = b.z;
        o0[6] = nx;   o0[7] = ny;   o0[8] = nz;
        o0[9] = lend;
        #pragma unroll
        for (int i = 0; i < 9; ++i) o0[10 + i] = B[i];

        o1[0] = b.x;  o1[1] = b.y;  o1[2] = b.z;
        o1[3] = a.x;  o1[4] = a.y;  o1[5] = a.z;
        o1[6] = -nx;  o1[7] = -ny;  o1[8] = -nz;
        o1[9] = lend;
        #pragma unroll
        for (int i = 0; i < 9; ++i) o1[10 + i] = B[i];
    }
}

extern "C" void kernel_launch(void* const* d_in, const int* in_sizes, int n_in,
                              void* d_out, int out_size) {
    const float* data   = (const float*)d_in[0];
    const int*   clusts = (const int*)d_in[1];
    const int*   eidx   = (const int*)d_in[2];
    float*       out    = (float*)d_out;

    const int n_edges = in_sizes[2] / 2;

    clust_geo_edge_kernel<<<n_edges, P>>>(data, clusts, eidx, out, n_edges);
}